// round 14
// baseline (speedup 1.0000x reference)
#include <cuda_runtime.h>
#include <cuda_bf16.h>

// LocalLoadBalancingLoss: B=65536, T=792, D=99, L=16.
// loss = mean_b[ var_{ddof=1}(u_b) + 0.5 * max(u_b) ], u = linkTraffic/(cap+1e-8)
//
// R14 = R13 phase-B kernel restructured into multi-tile blocks:
// 1024 blocks x 4 tiles x 16 rows, 512 thr, 2 smem buffers (ping-pong cp.async).
// Tile k+1's DRAM fetch is in flight during tile k's compute by construction;
// per-block tails (fence/atomic/stats) amortized 4x. Phase B loop unchanged.

#define NUM_T 792
#define NUM_D 99
#define NUM_L 16
#define ROWS 16
#define THREADS 512
#define PST 793                 // odd stride -> conflict-free LDS across rows
#define SETUP_THREADS 800
#define LSTRIDE 128             // u16 CSR slots per link, 256B-aligned slabs
#define TPB 4                   // tiles per block
#define GRID 1024               // 4096 tiles / TPB

#define SP_TILE (ROWS * PST)    // 12688 floats
#define SD_TILE (ROWS * NUM_D)  // 1584 floats

__device__ unsigned short g_pidx16[NUM_L * LSTRIDE];  // tunnel ids, per-link slabs
__device__ int   g_len[NUM_L];
__device__ float g_partials[GRID];
__device__ unsigned int g_done;

__device__ __forceinline__ void cpa4(unsigned dst, const float* src) {
    asm volatile("cp.async.ca.shared.global [%0], [%1], 4;" :: "r"(dst), "l"(src));
}

// ---------------------------------------------------------------------------
// Setup: fixed-stride link-sorted CSR (u16 tunnel ids). Identical to R13.
// ---------------------------------------------------------------------------
__global__ void llb_setup_kernel(const int* __restrict__ t2l) {
    __shared__ int s_wcnt[25][NUM_L];

    const int tid  = threadIdx.x;       // 800 = 25 warps
    const int w    = tid >> 5;
    const int lane = tid & 31;
    const bool act = (tid < NUM_T);

    if (tid < 25 * NUM_L) ((int*)s_wcnt)[tid] = 0;

    const int l = act ? t2l[tid] : 0;
    const int val = act ? l : (100 + lane);     // idle lanes -> singleton groups
    __syncthreads();

    unsigned m = __match_any_sync(0xFFFFFFFFu, val);
    const int rank = __popc(m & ((1u << lane) - 1u));
    if (act && lane == (__ffs(m) - 1)) s_wcnt[w][l] = __popc(m);
    __syncthreads();

    if (tid < NUM_L) {
        int acc = 0;
        for (int ww = 0; ww < 25; ww++) {
            int c = s_wcnt[ww][tid];
            s_wcnt[ww][tid] = acc;               // exclusive prefix over warps
            acc += c;
        }
        g_len[tid] = acc;
    }
    __syncthreads();

    if (act) g_pidx16[LSTRIDE * l + s_wcnt[w][l] + rank] = (unsigned short)tid;
    if (tid < NUM_L) {                           // zero padding slots
        int base = LSTRIDE * tid;
        for (int k = g_len[tid]; k < LSTRIDE; k++) g_pidx16[base + k] = 0;
    }
}

// ---------------------------------------------------------------------------
// Main: 1024 blocks, each 4 consecutive 16-row tiles, ping-pong buffers.
// ---------------------------------------------------------------------------
__global__ __launch_bounds__(THREADS, 2)
void llb_main_kernel(const float* __restrict__ pred,
                     const float* __restrict__ dem,
                     const float* __restrict__ cap,
                     float* __restrict__ out,
                     float inv_batch) {
    extern __shared__ float smem[];
    float* sp = smem;                            // [2][SP_TILE]
    float* sd = smem + 2 * SP_TILE;              // [2][SD_TILE]
    float* su = smem + 2 * SP_TILE + 2 * SD_TILE;// [16][17] stats scratch
    int*   sfl = (int*)(su + NUM_L * 17);

    const int tid  = threadIdx.x;
    const int w    = tid >> 5;           // link
    const int lane = tid & 31;
    const int part = lane >> 4;          // segment half
    const int r    = lane & 15;          // row

    // per-warp CSR segment metadata (identical to R13)
    const int   len  = g_len[w];
    int len0 = (((len + 1) >> 1) + 1) & ~1;      // half, rounded up to even
    if (len0 > len) len0 = len;
    const int   mybeg = LSTRIDE * w + (part ? len0 : 0);
    const int   mycnt = part ? (len - len0) : len0;
    const int   odd   = mybeg & 1;
    const float invc  = 1.0f / (cap[w] + 1e-8f);

    const unsigned spA = (unsigned)__cvta_generic_to_shared(sp);
    const unsigned sdA = (unsigned)__cvta_generic_to_shared(sd);
    const int base_tile = blockIdx.x * TPB;

    // prefetch tile (base_tile+j) into buffer q; always commits a group
    auto prefetch = [&](int j, int q) {
        if (j < TPB) {
            const float* gp = pred + (long long)(base_tile + j) * (ROWS * NUM_T);
            const float* gd = dem  + (long long)(base_tile + j) * (ROWS * NUM_D);
            #pragma unroll
            for (int k = 0; k < 25; k++) {
                int i = tid + k * THREADS;
                if (i < ROWS * NUM_T) {
                    int rr = (unsigned)i / NUM_T;        // smem idx = i + rr
                    cpa4(spA + 4u * (unsigned)(q * SP_TILE + i + rr), gp + i);
                }
            }
            #pragma unroll
            for (int k = 0; k < 4; k++) {
                int i = tid + k * THREADS;
                if (i < ROWS * NUM_D)
                    cpa4(sdA + 4u * (unsigned)(q * SD_TILE + i), gd + i);
            }
        }
        asm volatile("cp.async.commit_group;");
    };

    prefetch(0, 0);
    prefetch(1, 1);

    float pv = 0.f;                      // per-lane (row) loss partial, warp 0
    #pragma unroll
    for (int j = 0; j < TPB; j++) {
        const int p = j & 1;
        asm volatile("cp.async.wait_group 1;");  // tile j resident in buf p
        __syncthreads();

        // ---- phase B (identical to R13): half-warp walks half-segment ----
        const float* pr = sp + p * SP_TILE + r * PST;
        const float* dm = sd + p * SD_TILE + r * NUM_D;

        float s0 = 0.f, s1 = 0.f, s2 = 0.f, s3 = 0.f;
        int i = 0;
        if (odd && mycnt > 0) {                  // leading single -> even align
            int t = __ldg(g_pidx16 + mybeg);
            s0 += pr[t] * dm[t >> 3];
            i = 1;
        }
        for (; i + 3 < mycnt; i += 4) {          // u32 pair loads (4-aligned)
            unsigned q0 = __ldg((const unsigned*)(g_pidx16 + mybeg + i));
            unsigned q1 = __ldg((const unsigned*)(g_pidx16 + mybeg + i + 2));
            int t0 = q0 & 0xFFFFu, t1 = q0 >> 16;
            int t2 = q1 & 0xFFFFu, t3 = q1 >> 16;
            s0 += pr[t0] * dm[t0 >> 3];
            s1 += pr[t1] * dm[t1 >> 3];
            s2 += pr[t2] * dm[t2 >> 3];
            s3 += pr[t3] * dm[t3 >> 3];
        }
        for (; i < mycnt; i++) {                 // tail 0..3
            int t = __ldg(g_pidx16 + mybeg + i);
            s0 += pr[t] * dm[t >> 3];
        }
        float u = ((s0 + s1) + (s2 + s3)) * invc;
        u += __shfl_down_sync(0xFFFFFFFFu, u, 16);   // combine halves

        __syncthreads();                 // all reads of buf p complete

        prefetch(j + 2, p);              // DRAM for tile j+2 overlaps stats + j+1

        if (part == 0) su[w * 17 + r] = u;
        __syncthreads();

        // ---- per-row stats: warp 0 lanes 0-15 accumulate across tiles ----
        if (w == 0 && part == 0) {
            float sum = 0.f, mx = -1e30f;
            #pragma unroll
            for (int l = 0; l < NUM_L; l++) {
                float x = su[l * 17 + r];
                sum += x;
                mx = fmaxf(mx, x);
            }
            const float mean = sum * (1.0f / NUM_L);
            float var = 0.f;
            #pragma unroll
            for (int l = 0; l < NUM_L; l++) {
                float d = su[l * 17 + r] - mean;
                var += d * d;
            }
            var *= (1.0f / (NUM_L - 1));         // ddof = 1
            pv += var + 0.5f * mx;
        }
        // next iteration's post-wait barrier orders stats reads vs su rewrite
    }

    float bsum = 0.f;
    if (w == 0 && part == 0) {           // reduce 16 row-lanes once per block
        #pragma unroll
        for (int o = 8; o > 0; o >>= 1)
            pv += __shfl_down_sync(0x0000FFFFu, pv, o);
        bsum = pv;
    }
    if (tid == 0) g_partials[blockIdx.x] = bsum;

    // ---- fused deterministic reduction (R8 pattern), once per 4 tiles ----
    __threadfence();
    if (tid == 0) {
        unsigned n = atomicAdd(&g_done, 1u);
        sfl[0] = (n == (unsigned)(gridDim.x - 1)) ? 1 : 0;
    }
    __syncthreads();
    if (sfl[0]) {
        __threadfence();
        float v = g_partials[tid] + g_partials[tid + THREADS];   // fixed order
        float* rb = sp;                          // reuse smem
        rb[tid] = v;
        __syncthreads();
        #pragma unroll
        for (int s = THREADS / 2; s > 0; s >>= 1) {
            if (tid < s) rb[tid] += rb[tid + s]; // fixed pairing -> deterministic
            __syncthreads();
        }
        if (tid == 0) {
            out[0] = rb[0] * inv_batch;
            g_done = 0;                          // reset for next graph replay
        }
    }
}

extern "C" void kernel_launch(void* const* d_in, const int* in_sizes, int n_in,
                              void* d_out, int out_size) {
    const float* pred = (const float*)d_in[0];   // [B, 792]
    const float* dem  = (const float*)d_in[1];   // [B, 99]
    const int*   t2l  = (const int*)d_in[2];     // [792]
    const float* cap  = (const float*)d_in[3];   // [16]
    float* out = (float*)d_out;

    const int B = in_sizes[1] / NUM_D;           // 65536
    const int nblocks = B / (ROWS * TPB);        // 1024

    // 2 pred buffers + 2 dem buffers + su[16][17] + flag
    const int smem_bytes = (2 * SP_TILE + 2 * SD_TILE + NUM_L * 17) * (int)sizeof(float)
                         + (int)sizeof(int);     // 115268
    static bool attr_set = false;
    if (!attr_set) {
        cudaFuncSetAttribute(llb_main_kernel,
                             cudaFuncAttributeMaxDynamicSharedMemorySize, smem_bytes);
        attr_set = true;
    }

    llb_setup_kernel<<<1, SETUP_THREADS>>>(t2l);
    llb_main_kernel<<<nblocks, THREADS, smem_bytes>>>(pred, dem, cap, out,
                                                      1.0f / (float)B);
}